// round 11
// baseline (speedup 1.0000x reference)
#include <cuda_runtime.h>
#include <cuda_fp16.h>
#include <math.h>
#include <stdint.h>

// ---------------- problem constants ----------------
#define NPIX     32768
#define NE       1024
#define KDIM     256
#define BETA     0.25f
#define EPS_P    1e-10f
#define DELTA    0.25f

// output layout (concatenated, float32)
#define ZQ_OFF    1ull
#define PERP_OFF  8388609ull
#define IDX_OFF   8388610ull
#define ZQ1_OFF   8421378ull

// ---------------- device scratch ----------------
__device__ int    g_idx[NPIX];
__device__ float  g_hn_g[NE];
__device__ int    g_hist[NE];
__device__ float  g_partials[1024];
__device__ int    g_cnt[NPIX];
__device__ int    g_cand[NPIX * 8];
// emb fp16, chunk-major packed: [64 chunks][128 codes][32 halfs], k perm16'd within 16-blocks
__device__ __half g_eh[64 * 128 * 32];

// ---------------- argmin smem byte offsets ----------------
#define SMB_AS    0            // 256 x 264 halfs = 135168
#define SMB_BS    135168       // 3 x (128 x 40 halfs) = 30720
#define SMB_STG   165888       // 32 x 264 floats = 33792
#define SMB_HN    199680       // 1024 floats
#define SMB_REDV  203776       // 256 x 4 floats = 4096
#define SMB_VS    207872       // 256 floats
#define SMB_TOTAL 208896
#define B_STAGE_H 5120

// ---------------- fused rescore+gather smem byte offsets ----------------
#define RG_ZS     0            // 32 x 257 floats = 32896
#define RG_SE     32896        // 32 x 257 floats = 32896
#define RG_SIDX   65792        // 32 ints
#define RG_RED    65920        // 256 floats
#define RG_TOTAL  66944

static __device__ __forceinline__ uint32_t smem_u32(const void* p) {
    uint32_t a;
    asm("{ .reg .u64 t; cvta.to.shared.u64 t, %1; cvt.u32.u64 %0, t; }" : "=r"(a) : "l"(p));
    return a;
}
static __device__ __forceinline__ void cp16(uint32_t smem, const void* g) {
    asm volatile("cp.async.cg.shared.global [%0], [%1], 16;" :: "r"(smem), "l"(g) : "memory");
}
#define CP_COMMIT() asm volatile("cp.async.commit_group;" ::: "memory")
#define CP_WAIT1()  asm volatile("cp.async.wait_group 1;" ::: "memory")
#define CP_WAIT0()  asm volatile("cp.async.wait_group 0;" ::: "memory")

static __device__ __forceinline__ void mma16(float* c, const uint32_t* a, uint32_t b0, uint32_t b1) {
    asm volatile(
        "mma.sync.aligned.m16n8k16.row.col.f32.f16.f16.f32 "
        "{%0,%1,%2,%3}, {%4,%5,%6,%7}, {%8,%9}, {%0,%1,%2,%3};"
        : "+f"(c[0]), "+f"(c[1]), "+f"(c[2]), "+f"(c[3])
        : "r"(a[0]), "r"(a[1]), "r"(a[2]), "r"(a[3]), "r"(b0), "r"(b1));
}

// permutation within 16-blocks so fragment k-quads {2qc,2qc+1,2qc+8,2qc+9} are contiguous
static __device__ __forceinline__ int perm16(int j) {
    return ((j >> 1) & 3) * 4 + ((j >> 3) & 1) * 2 + (j & 1);
}

// ---------------- dummy kernels (keep argmin as launch #4 for ncu) ----------------
__global__ void dummy1_kernel() {}
__global__ void dummy2_kernel() {}

// ---------------- kernel 0: emb -> fp16 chunk-major + half norms + zero ----------------
__global__ void split_kernel(const float* __restrict__ emb) {
    __shared__ float red[256];
    const int c = blockIdx.x;        // code 0..1023
    const int t = threadIdx.x;       // k 0..255
    float f = emb[c * KDIM + t];
    int chunk = (c >> 7) * 8 + (t >> 5);
    int within = (t & 16) + perm16(t & 15);
    g_eh[chunk * 4096 + (c & 127) * 32 + within] = __float2half_rn(f);
    red[t] = f * f;
    int gid = c * 256 + t;
    if (gid < NPIX) g_cnt[gid] = 0;
    __syncthreads();
    #pragma unroll
    for (int s = 128; s > 0; s >>= 1) {
        if (t < s) red[t] += red[t + s];
        __syncthreads();
    }
    if (t == 0) { g_hn_g[c] = 0.5f * red[0]; g_hist[c] = 0; }
}

// ---------------- kernel A: fp16 mma approximate argmax, 1024 threads ----------------
// 32 warps = 8 M-groups x 4 N-groups; warp tile 32(M) x 32(N). MT=256 pixels/CTA.
__global__ void __launch_bounds__(1024, 1)
argmin_mma_kernel(const float* __restrict__ z) {
    extern __shared__ char smc[];
    __half* As  = (__half*)(smc + SMB_AS);     // [256][264]
    __half* Bsb = (__half*)(smc + SMB_BS);     // 3 x [128][40]
    float* stg  = (float*)(smc + SMB_STG);     // [32][264]
    float* hn   = (float*)(smc + SMB_HN);
    float* redv = (float*)(smc + SMB_REDV);    // [256][4]
    float* Vs   = (float*)(smc + SMB_VS);
    const uint32_t sb = smem_u32(smc);

    const int tid = threadIdx.x;
    const int wid = tid >> 5;
    const int l   = tid & 31;
    const int qr  = l >> 2;
    const int qc  = l & 3;
    const int mb  = (wid >> 2) * 32;
    const int nb  = (wid & 3) * 32;
    const int m0  = blockIdx.x * 256;

    // B chunk loader: 8KB packed global -> padded smem stage (512 cp16 by lower half)
    auto load_chunk = [&](int it, int stage) {
        if (tid < 512) {
            const char* src = (const char*)g_eh + (size_t)it * 8192;
            uint32_t dst = sb + SMB_BS + stage * 10240;
            int code = tid >> 2, j = tid & 3;
            cp16(dst + code * 80 + j * 16, src + code * 64 + j * 16);
        }
        CP_COMMIT();
    };

    load_chunk(0, 0);
    load_chunk(1, 1);

    // ---- prologue: z (256 px x 256 k) -> fp16 As, k perm16'd ----
    {
        const float* zb = z + (size_t)(m0 >> 10) * (KDIM * 1024) + (m0 & 1023);
        const int m = tid & 255, hh = tid >> 8;   // hh 0..3
        for (int g = 0; g < 8; g++) {
            __syncthreads();
            #pragma unroll
            for (int r = 0; r < 2; r++) {
                int q = tid + 1024 * r;         // 0..2047 float4s
                int kk = q >> 6;                // 0..31
                int m4 = (q & 63) << 2;         // 0..252
                float4 v = *(const float4*)(zb + (size_t)(g * 32 + kk) * 1024 + m4);
                *(float4*)(stg + kk * 264 + m4) = v;
            }
            __syncthreads();
            #pragma unroll
            for (int pp = 0; pp < 4; pp++) {
                int p = hh * 4 + pp;            // 0..15 half2 pairs
                float f0 = stg[(2 * p) * 264 + m];
                float f1 = stg[(2 * p + 1) * 264 + m];
                int dest = ((p >> 3) & 1) * 16 + (p & 3) * 4 + ((p >> 2) & 1) * 2;
                __half2 h = __floats2half2_rn(f0, f1);
                *(__half2*)(As + m * 264 + g * 32 + dest) = h;
            }
        }
        hn[tid] = g_hn_g[tid];
    }
    __syncthreads();

    // per-slot running best + 2 runner-ups within DELTA (4 slots = 4 row-groups)
    float best[4]; int bidx[4];
    float cv[4][2]; int ci[4][2];
    #pragma unroll
    for (int s = 0; s < 4; s++) {
        best[s] = -INFINITY; bidx[s] = 0;
        cv[s][0] = -INFINITY; cv[s][1] = -INFINITY;
        ci[s][0] = 0; ci[s][1] = 0;
    }

    for (int ct = 0; ct < 8; ct++) {
        float acc[2][4][4];
        #pragma unroll
        for (int mf = 0; mf < 2; mf++)
            #pragma unroll
            for (int nf = 0; nf < 4; nf++)
                #pragma unroll
                for (int cc = 0; cc < 4; cc++) acc[mf][nf][cc] = 0.0f;

        for (int kc = 0; kc < 8; kc++) {
            const int it = ct * 8 + kc;
            const int stage = it % 3;
            if (it == 63) { CP_WAIT0(); } else { CP_WAIT1(); }
            __syncthreads();
            if (it + 2 < 64) load_chunk(it + 2, (it + 2) % 3);

            const __half* B = Bsb + stage * B_STAGE_H;

            #pragma unroll
            for (int ks = 0; ks < 2; ks++) {
                uint32_t af[2][4];
                #pragma unroll
                for (int mf = 0; mf < 2; mf++) {
                    int r0 = mb + qr + mf * 16;
                    uint2 A1 = *(const uint2*)(As + r0 * 264 + kc * 32 + ks * 16 + qc * 4);
                    uint2 A2 = *(const uint2*)(As + (r0 + 8) * 264 + kc * 32 + ks * 16 + qc * 4);
                    af[mf][0] = A1.x; af[mf][2] = A1.y;
                    af[mf][1] = A2.x; af[mf][3] = A2.y;
                }
                #pragma unroll
                for (int nf = 0; nf < 4; nf++) {
                    int n = nb + nf * 8 + qr;
                    uint2 B2 = *(const uint2*)(B + n * 40 + ks * 16 + qc * 4);
                    mma16(acc[0][nf], af[0], B2.x, B2.y);
                    mma16(acc[1][nf], af[1], B2.x, B2.y);
                }
            }
        }

        // epilogue: subtract half-norm, fold into running argmax + candidate lists
        #pragma unroll
        for (int mf = 0; mf < 2; mf++)
            #pragma unroll
            for (int nf = 0; nf < 4; nf++)
                #pragma unroll
                for (int cc = 0; cc < 4; cc++) {
                    int col = nb + nf * 8 + 2 * qc + (cc & 1);
                    int code = ct * 128 + col;
                    float s = acc[mf][nf][cc] - hn[code];
                    int slot = mf * 2 + (cc >> 1);
                    if (s > best[slot]) {
                        float ov = best[slot]; int oi = bidx[slot];
                        if (cv[slot][0] <= cv[slot][1]) {
                            if (ov > cv[slot][0]) { cv[slot][0] = ov; ci[slot][0] = oi; }
                        } else {
                            if (ov > cv[slot][1]) { cv[slot][1] = ov; ci[slot][1] = oi; }
                        }
                        best[slot] = s; bidx[slot] = code;
                    } else if (s > best[slot] - DELTA) {
                        if (cv[slot][0] <= cv[slot][1]) {
                            if (s > cv[slot][0]) { cv[slot][0] = s; ci[slot][0] = code; }
                        } else {
                            if (s > cv[slot][1]) { cv[slot][1] = s; ci[slot][1] = code; }
                        }
                    }
                }
    }

    // per-pixel approx max: qc-lane reduce, then the 4 N-warps via smem
    #pragma unroll
    for (int s = 0; s < 4; s++) {
        float v = best[s];
        #pragma unroll
        for (int m = 1; m <= 2; m <<= 1) {
            float ov = __shfl_xor_sync(0xffffffffu, v, m);
            if (ov > v) v = ov;
        }
        if (qc == 0) {
            int row = mb + qr + (s >> 1) * 16 + (s & 1) * 8;
            redv[row * 4 + (wid & 3)] = v;
        }
    }
    __syncthreads();
    if (tid < 256) {
        float v = fmaxf(fmaxf(redv[tid * 4], redv[tid * 4 + 1]),
                        fmaxf(redv[tid * 4 + 2], redv[tid * 4 + 3]));
        Vs[tid] = v;
    }
    __syncthreads();

    // emit candidates within DELTA of pixel approx max
    #pragma unroll
    for (int s = 0; s < 4; s++) {
        int row = mb + qr + (s >> 1) * 16 + (s & 1) * 8;
        float V = Vs[row];
        int p = m0 + row;
        if (best[s] > V - DELTA) {
            int pos = atomicAdd(&g_cnt[p], 1);
            if (pos < 8) g_cand[p * 8 + pos] = bidx[s];
        }
        if (cv[s][0] > V - DELTA) {
            int pos = atomicAdd(&g_cnt[p], 1);
            if (pos < 8) g_cand[p * 8 + pos] = ci[s][0];
        }
        if (cv[s][1] > V - DELTA) {
            int pos = atomicAdd(&g_cnt[p], 1);
            if (pos < 8) g_cand[p * 8 + pos] = ci[s][1];
        }
    }
}

// ---------------- kernel B: fused exact rescore + gather + partials ----------------
// 256 threads, 32 pixels per block. z staged once; gather reads it from smem.
__global__ void __launch_bounds__(256)
rescore_gather_kernel(const float* __restrict__ z, const float* __restrict__ emb,
                      float* __restrict__ out) {
    extern __shared__ char smc[];
    float* zs  = (float*)(smc + RG_ZS);     // [32][257]  zs[pixel][k]
    float* se  = (float*)(smc + RG_SE);     // [32][257]  se[pixel][k]
    int* sidx  = (int*)(smc + RG_SIDX);
    float* red = (float*)(smc + RG_RED);

    const int t = threadIdx.x;
    const int w = t >> 5;
    const int l = t & 31;
    const int n0 = blockIdx.x * 32;
    const int b = n0 >> 10;
    const float* zb = z + (size_t)b * (KDIM * 1024) + (n0 & 1023);

    // stage z: zs[pixel][k], coalesced
    #pragma unroll
    for (int r = 0; r < 8; r++) {
        int q = t + 256 * r;            // 0..2047
        int kk = q >> 3;                // k 0..255
        int h4 = (q & 7) << 2;          // pixel 0..28
        float4 v = *(const float4*)(zb + (size_t)kk * 1024 + h4);
        zs[(h4 + 0) * 257 + kk] = v.x; zs[(h4 + 1) * 257 + kk] = v.y;
        zs[(h4 + 2) * 257 + kk] = v.z; zs[(h4 + 3) * 257 + kk] = v.w;
    }
    __syncthreads();

    // exact fp32 rescore: warp w handles pixels w*4..w*4+3
    #pragma unroll
    for (int px = 0; px < 4; px++) {
        int pix = w * 4 + px;
        int p = n0 + pix;
        int cnt = g_cnt[p];
        if (cnt > 8) cnt = 8;
        float bestv = -INFINITY;
        int besti = 0;
        for (int c = 0; c < cnt; c++) {
            int idx = g_cand[p * 8 + c];
            const float* e = emb + (size_t)idx * KDIM;
            float acc = 0.0f;
            #pragma unroll
            for (int j = 0; j < 8; j++)
                acc = fmaf(zs[pix * 257 + j * 32 + l], e[j * 32 + l], acc);
            #pragma unroll
            for (int m = 16; m >= 1; m >>= 1)
                acc += __shfl_xor_sync(0xffffffffu, acc, m);
            float s = acc - g_hn_g[idx];
            if (s > bestv || (s == bestv && idx < besti)) { bestv = s; besti = idx; }
        }
        if (l == 0) {
            sidx[pix] = besti;
            g_idx[p] = besti;
            out[IDX_OFF + p] = (float)besti;
        }
    }
    __syncthreads();

    // load emb rows of the final indices: se[pixel][k]
    #pragma unroll
    for (int r = 0; r < 8; r++) {
        int q = t + 256 * r;
        int row = q >> 6;               // pixel 0..31
        int c4 = (q & 63) << 2;         // k 0..252
        float4 v = *(const float4*)(emb + (size_t)sidx[row] * KDIM + c4);
        se[row * 257 + c4 + 0] = v.x; se[row * 257 + c4 + 1] = v.y;
        se[row * 257 + c4 + 2] = v.z; se[row * 257 + c4 + 3] = v.w;
    }
    __syncthreads();

    // gather: write z_q / z_q1, accumulate squared error (z from smem)
    const int hw = t & 31;
    const int cg = t >> 5;
    const int hwg = (n0 & 1023) + hw;
    const size_t zbase = (size_t)b * (KDIM * 1024) + hwg;
    float acc = 0.0f;
    #pragma unroll
    for (int ci2 = 0; ci2 < 32; ci2++) {
        int c = cg * 32 + ci2;
        float v = se[hw * 257 + c];
        float zv = zs[hw * 257 + c];
        size_t off = zbase + (size_t)c * 1024;
        float d = v - zv;
        acc += d * d;
        out[ZQ_OFF + off] = v;
        out[ZQ1_OFF + off] = v;
    }
    red[t] = acc;
    __syncthreads();
    #pragma unroll
    for (int s = 128; s > 0; s >>= 1) {
        if (t < s) red[t] += red[t + s];
        __syncthreads();
    }
    if (t == 0) g_partials[blockIdx.x] = red[0];
}

// ---------------- kernel C: parallel histogram ----------------
__global__ void hist_kernel() {
    __shared__ int h[NE];
    const int t = threadIdx.x;       // 32 blocks x 256 threads
    #pragma unroll
    for (int r = 0; r < 4; r++) h[t + 256 * r] = 0;
    __syncthreads();
    const int base = blockIdx.x * 1024;
    #pragma unroll
    for (int r = 0; r < 4; r++) {
        int id = g_idx[base + t + 256 * r];
        atomicAdd(&h[id], 1);
    }
    __syncthreads();
    #pragma unroll
    for (int r = 0; r < 4; r++) {
        int v = h[t + 256 * r];
        if (v) atomicAdd(&g_hist[t + 256 * r], v);
    }
}

// ---------------- kernel D: loss + perplexity ----------------
__global__ void finalize_kernel(float* __restrict__ out) {
    __shared__ float red[1024];
    const int t = threadIdx.x;       // 1024 threads, 1 block
    red[t] = g_partials[t];
    __syncthreads();
    #pragma unroll
    for (int s = 512; s > 0; s >>= 1) {
        if (t < s) red[t] += red[t + s];
        __syncthreads();
    }
    float loss = red[0] * (1.0f + BETA) / 8388608.0f;
    __syncthreads();
    float p = (float)g_hist[t] / (float)NPIX;
    red[t] = p * logf(p + EPS_P);
    __syncthreads();
    #pragma unroll
    for (int s = 512; s > 0; s >>= 1) {
        if (t < s) red[t] += red[t + s];
        __syncthreads();
    }
    if (t == 0) {
        out[0] = loss;
        out[PERP_OFF] = expf(-red[0]);
    }
}

// ---------------- launch ----------------
extern "C" void kernel_launch(void* const* d_in, const int* in_sizes, int n_in,
                              void* d_out, int out_size) {
    const float* z   = (const float*)d_in[0];
    const float* emb = (const float*)d_in[1];
    float* out = (float*)d_out;

    split_kernel<<<NE, 256>>>(emb);
    dummy1_kernel<<<1, 32>>>();      // ncu alignment: argmin stays launch #4
    dummy2_kernel<<<1, 32>>>();

    cudaFuncSetAttribute(argmin_mma_kernel,
                         cudaFuncAttributeMaxDynamicSharedMemorySize, SMB_TOTAL);
    argmin_mma_kernel<<<NPIX / 256, 1024, SMB_TOTAL>>>(z);

    cudaFuncSetAttribute(rescore_gather_kernel,
                         cudaFuncAttributeMaxDynamicSharedMemorySize, RG_TOTAL);
    rescore_gather_kernel<<<NPIX / 32, 256, RG_TOTAL>>>(z, emb, out);

    hist_kernel<<<32, 256>>>();
    finalize_kernel<<<1, 1024>>>(out);
}

// round 13
// speedup vs baseline: 1.3244x; 1.3244x over previous
#include <cuda_runtime.h>
#include <cuda_fp16.h>
#include <math.h>
#include <stdint.h>

// ---------------- problem constants ----------------
#define NPIX     32768
#define NE       1024
#define KDIM     256
#define BETA     0.25f
#define EPS_P    1e-10f
#define DELTA    0.25f

// output layout (concatenated, float32)
#define ZQ_OFF    1ull
#define PERP_OFF  8388609ull
#define IDX_OFF   8388610ull
#define ZQ1_OFF   8421378ull

// ---------------- device scratch ----------------
__device__ int    g_idx[NPIX];
__device__ float  g_hn_g[NE];
__device__ int    g_hist[NE];
__device__ float  g_partials[1024];
__device__ int    g_cnt[NPIX];
__device__ int    g_cand[NPIX * 8];
// emb fp16, chunk-major packed: [64 chunks][128 codes][32 halfs], k perm16'd within 16-blocks
__device__ __half g_eh[64 * 128 * 32];

// ---------------- argmin smem byte offsets ----------------
#define SMB_AS    0            // 256 x 264 halfs = 135168
#define SMB_BS    135168       // 3 x (128 x 40 halfs) = 30720
#define SMB_STG   165888       // 32 x 264 floats = 33792
#define SMB_HN    199680       // 1024 floats
#define SMB_REDV  203776       // 256 x 2 floats = 2048
#define SMB_VS    205824       // 256 floats
#define SMB_TOTAL 206848
#define B_STAGE_H 5120

static __device__ __forceinline__ uint32_t smem_u32(const void* p) {
    uint32_t a;
    asm("{ .reg .u64 t; cvta.to.shared.u64 t, %1; cvt.u32.u64 %0, t; }" : "=r"(a) : "l"(p));
    return a;
}
static __device__ __forceinline__ void cp16(uint32_t smem, const void* g) {
    asm volatile("cp.async.cg.shared.global [%0], [%1], 16;" :: "r"(smem), "l"(g) : "memory");
}
#define CP_COMMIT() asm volatile("cp.async.commit_group;" ::: "memory")
#define CP_WAIT1()  asm volatile("cp.async.wait_group 1;" ::: "memory")
#define CP_WAIT0()  asm volatile("cp.async.wait_group 0;" ::: "memory")

static __device__ __forceinline__ void mma16(float* c, const uint32_t* a, uint32_t b0, uint32_t b1) {
    asm volatile(
        "mma.sync.aligned.m16n8k16.row.col.f32.f16.f16.f32 "
        "{%0,%1,%2,%3}, {%4,%5,%6,%7}, {%8,%9}, {%0,%1,%2,%3};"
        : "+f"(c[0]), "+f"(c[1]), "+f"(c[2]), "+f"(c[3])
        : "r"(a[0]), "r"(a[1]), "r"(a[2]), "r"(a[3]), "r"(b0), "r"(b1));
}

// permutation within 16-blocks so fragment k-quads {2qc,2qc+1,2qc+8,2qc+9} are contiguous
static __device__ __forceinline__ int perm16(int j) {
    return ((j >> 1) & 3) * 4 + ((j >> 3) & 1) * 2 + (j & 1);
}

// ---------------- dummy kernels (keep argmin as launch #4 for ncu) ----------------
__global__ void dummy1_kernel() {}
__global__ void dummy2_kernel() {}

// ---------------- kernel 0: emb -> fp16 chunk-major + half norms + zero ----------------
__global__ void split_kernel(const float* __restrict__ emb) {
    __shared__ float red[256];
    const int c = blockIdx.x;        // code 0..1023
    const int t = threadIdx.x;       // k 0..255
    float f = emb[c * KDIM + t];
    int chunk = (c >> 7) * 8 + (t >> 5);
    int within = (t & 16) + perm16(t & 15);
    g_eh[chunk * 4096 + (c & 127) * 32 + within] = __float2half_rn(f);
    red[t] = f * f;
    int gid = c * 256 + t;
    if (gid < NPIX) g_cnt[gid] = 0;
    __syncthreads();
    #pragma unroll
    for (int s = 128; s > 0; s >>= 1) {
        if (t < s) red[t] += red[t + s];
        __syncthreads();
    }
    if (t == 0) { g_hn_g[c] = 0.5f * red[0]; g_hist[c] = 0; }
}

// ---------------- kernel A: fp16 mma approximate argmax, 1024 threads ----------------
// 32 warps = 16 M-groups x 2 N-groups; warp tile 16(M) x 64(N). MT=256 pixels/CTA.
// Per-thread: 2 pixel-row slots, acc[8][4] -> fits 64 regs without spill.
__global__ void __launch_bounds__(1024, 1)
argmin_mma_kernel(const float* __restrict__ z) {
    extern __shared__ char smc[];
    __half* As  = (__half*)(smc + SMB_AS);     // [256][264]
    __half* Bsb = (__half*)(smc + SMB_BS);     // 3 x [128][40]
    float* stg  = (float*)(smc + SMB_STG);     // [32][264]
    float* hn   = (float*)(smc + SMB_HN);
    float* redv = (float*)(smc + SMB_REDV);    // [256][2]
    float* Vs   = (float*)(smc + SMB_VS);
    const uint32_t sb = smem_u32(smc);

    const int tid = threadIdx.x;
    const int wid = tid >> 5;
    const int l   = tid & 31;
    const int qr  = l >> 2;
    const int qc  = l & 3;
    const int mb  = (wid >> 1) * 16;
    const int nb  = (wid & 1) * 64;
    const int m0  = blockIdx.x * 256;

    // B chunk loader: 8KB packed global -> padded smem stage (512 cp16 by lower half)
    auto load_chunk = [&](int it, int stage) {
        if (tid < 512) {
            const char* src = (const char*)g_eh + (size_t)it * 8192;
            uint32_t dst = sb + SMB_BS + stage * 10240;
            int code = tid >> 2, j = tid & 3;
            cp16(dst + code * 80 + j * 16, src + code * 64 + j * 16);
        }
        CP_COMMIT();
    };

    load_chunk(0, 0);
    load_chunk(1, 1);

    // ---- prologue: z (256 px x 256 k) -> fp16 As, k perm16'd ----
    {
        const float* zb = z + (size_t)(m0 >> 10) * (KDIM * 1024) + (m0 & 1023);
        const int m = tid & 255, hh = tid >> 8;   // hh 0..3
        for (int g = 0; g < 8; g++) {
            __syncthreads();
            #pragma unroll
            for (int r = 0; r < 2; r++) {
                int q = tid + 1024 * r;         // 0..2047 float4s
                int kk = q >> 6;                // 0..31
                int m4 = (q & 63) << 2;         // 0..252
                float4 v = *(const float4*)(zb + (size_t)(g * 32 + kk) * 1024 + m4);
                *(float4*)(stg + kk * 264 + m4) = v;
            }
            __syncthreads();
            #pragma unroll
            for (int pp = 0; pp < 4; pp++) {
                int p = hh * 4 + pp;            // 0..15 half2 pairs
                float f0 = stg[(2 * p) * 264 + m];
                float f1 = stg[(2 * p + 1) * 264 + m];
                int dest = ((p >> 3) & 1) * 16 + (p & 3) * 4 + ((p >> 2) & 1) * 2;
                __half2 h = __floats2half2_rn(f0, f1);
                *(__half2*)(As + m * 264 + g * 32 + dest) = h;
            }
        }
        hn[tid] = g_hn_g[tid];
    }
    __syncthreads();

    // per-slot running best + 2 runner-ups within DELTA (2 slots = 2 pixel rows)
    float best[2]; int bidx[2];
    float cv[2][2]; int ci[2][2];
    #pragma unroll
    for (int s = 0; s < 2; s++) {
        best[s] = -INFINITY; bidx[s] = 0;
        cv[s][0] = -INFINITY; cv[s][1] = -INFINITY;
        ci[s][0] = 0; ci[s][1] = 0;
    }

    for (int ct = 0; ct < 8; ct++) {
        float acc[8][4];
        #pragma unroll
        for (int nf = 0; nf < 8; nf++)
            #pragma unroll
            for (int cc = 0; cc < 4; cc++) acc[nf][cc] = 0.0f;

        for (int kc = 0; kc < 8; kc++) {
            const int it = ct * 8 + kc;
            const int stage = it % 3;
            if (it == 63) { CP_WAIT0(); } else { CP_WAIT1(); }
            __syncthreads();
            if (it + 2 < 64) load_chunk(it + 2, (it + 2) % 3);

            const __half* B = Bsb + stage * B_STAGE_H;

            #pragma unroll
            for (int ks = 0; ks < 2; ks++) {
                uint32_t af[4];
                {
                    int r0 = mb + qr;
                    uint2 A1 = *(const uint2*)(As + r0 * 264 + kc * 32 + ks * 16 + qc * 4);
                    uint2 A2 = *(const uint2*)(As + (r0 + 8) * 264 + kc * 32 + ks * 16 + qc * 4);
                    af[0] = A1.x; af[2] = A1.y;
                    af[1] = A2.x; af[3] = A2.y;
                }
                #pragma unroll
                for (int nf = 0; nf < 8; nf++) {
                    int n = nb + nf * 8 + qr;
                    uint2 B2 = *(const uint2*)(B + n * 40 + ks * 16 + qc * 4);
                    mma16(acc[nf], af, B2.x, B2.y);
                }
            }
        }

        // epilogue: subtract half-norm, fold into running argmax + candidate lists
        #pragma unroll
        for (int nf = 0; nf < 8; nf++)
            #pragma unroll
            for (int cc = 0; cc < 4; cc++) {
                int col = nb + nf * 8 + 2 * qc + (cc & 1);
                int code = ct * 128 + col;
                float s = acc[nf][cc] - hn[code];
                int slot = cc >> 1;
                if (s > best[slot]) {
                    float ov = best[slot]; int oi = bidx[slot];
                    if (cv[slot][0] <= cv[slot][1]) {
                        if (ov > cv[slot][0]) { cv[slot][0] = ov; ci[slot][0] = oi; }
                    } else {
                        if (ov > cv[slot][1]) { cv[slot][1] = ov; ci[slot][1] = oi; }
                    }
                    best[slot] = s; bidx[slot] = code;
                } else if (s > best[slot] - DELTA) {
                    if (cv[slot][0] <= cv[slot][1]) {
                        if (s > cv[slot][0]) { cv[slot][0] = s; ci[slot][0] = code; }
                    } else {
                        if (s > cv[slot][1]) { cv[slot][1] = s; ci[slot][1] = code; }
                    }
                }
            }
    }

    // per-pixel approx max: qc-lane reduce, then the 2 N-warps via smem
    #pragma unroll
    for (int s = 0; s < 2; s++) {
        float v = best[s];
        #pragma unroll
        for (int m = 1; m <= 2; m <<= 1) {
            float ov = __shfl_xor_sync(0xffffffffu, v, m);
            if (ov > v) v = ov;
        }
        if (qc == 0) {
            int row = mb + qr + s * 8;
            redv[row * 2 + (wid & 1)] = v;
        }
    }
    __syncthreads();
    if (tid < 256) Vs[tid] = fmaxf(redv[tid * 2], redv[tid * 2 + 1]);
    __syncthreads();

    // emit candidates within DELTA of pixel approx max
    #pragma unroll
    for (int s = 0; s < 2; s++) {
        int row = mb + qr + s * 8;
        float V = Vs[row];
        int p = m0 + row;
        if (best[s] > V - DELTA) {
            int pos = atomicAdd(&g_cnt[p], 1);
            if (pos < 8) g_cand[p * 8 + pos] = bidx[s];
        }
        if (cv[s][0] > V - DELTA) {
            int pos = atomicAdd(&g_cnt[p], 1);
            if (pos < 8) g_cand[p * 8 + pos] = ci[s][0];
        }
        if (cv[s][1] > V - DELTA) {
            int pos = atomicAdd(&g_cnt[p], 1);
            if (pos < 8) g_cand[p * 8 + pos] = ci[s][1];
        }
    }
}

// ---------------- kernel A2: exact fp32 rescoring (smem-staged z, coalesced) ----------------
__global__ void __launch_bounds__(256)
rescore_kernel(const float* __restrict__ z, const float* __restrict__ emb) {
    __shared__ float zs[32][257];
    const int t = threadIdx.x;
    const int w = t >> 5;
    const int l = t & 31;
    const int n0 = blockIdx.x * 32;
    const int b = n0 >> 10;
    const float* zb = z + (size_t)b * (KDIM * 1024) + (n0 & 1023);
    #pragma unroll
    for (int r = 0; r < 8; r++) {
        int q = t + 256 * r;            // 0..2047
        int kk = q >> 3;                // 0..255
        int h4 = (q & 7) << 2;          // 0..28
        float4 v = *(const float4*)(zb + (size_t)kk * 1024 + h4);
        zs[h4 + 0][kk] = v.x; zs[h4 + 1][kk] = v.y;
        zs[h4 + 2][kk] = v.z; zs[h4 + 3][kk] = v.w;
    }
    __syncthreads();
    #pragma unroll
    for (int px = 0; px < 4; px++) {
        int pix = w * 4 + px;
        int p = n0 + pix;
        int cnt = g_cnt[p];
        if (cnt > 8) cnt = 8;
        float bestv = -INFINITY;
        int besti = 0;
        for (int c = 0; c < cnt; c++) {
            int idx = g_cand[p * 8 + c];
            const float* e = emb + (size_t)idx * KDIM;
            float acc = 0.0f;
            #pragma unroll
            for (int j = 0; j < 8; j++)
                acc = fmaf(zs[pix][j * 32 + l], e[j * 32 + l], acc);
            #pragma unroll
            for (int m = 16; m >= 1; m >>= 1)
                acc += __shfl_xor_sync(0xffffffffu, acc, m);
            float s = acc - g_hn_g[idx];
            if (s > bestv || (s == bestv && idx < besti)) { bestv = s; besti = idx; }
        }
        if (l == 0) g_idx[p] = besti;
    }
}

// ---------------- kernel B1: gather z_q/z_q1 + squared-error partials + idx out ----------------
__global__ void __launch_bounds__(256)
gather_kernel(const float* __restrict__ z, const float* __restrict__ emb,
              float* __restrict__ out) {
    __shared__ float se[32][257];
    __shared__ int sidx[32];
    __shared__ float red[256];
    const int t = threadIdx.x;
    const int n0 = blockIdx.x * 32;
    if (t < 32) sidx[t] = g_idx[n0 + t];
    __syncthreads();
    if (t < 32) out[IDX_OFF + n0 + t] = (float)sidx[t];
    #pragma unroll
    for (int r = 0; r < 8; r++) {
        int q = t + 256 * r;
        int row = q >> 6;
        int c4 = (q & 63) << 2;
        float4 v = *(const float4*)(emb + (size_t)sidx[row] * KDIM + c4);
        se[row][c4 + 0] = v.x; se[row][c4 + 1] = v.y;
        se[row][c4 + 2] = v.z; se[row][c4 + 3] = v.w;
    }
    __syncthreads();
    const int hw = t & 31;
    const int cg = t >> 5;
    const int b = n0 >> 10;
    const int hwg = (n0 & 1023) + hw;
    const size_t zbase = (size_t)b * (KDIM * 1024) + hwg;
    float acc = 0.0f;
    #pragma unroll
    for (int ci2 = 0; ci2 < 32; ci2++) {
        int c = cg * 32 + ci2;
        float v = se[hw][c];
        size_t off = zbase + (size_t)c * 1024;
        float zv = z[off];
        float d = v - zv;
        acc += d * d;
        out[ZQ_OFF + off] = v;
        out[ZQ1_OFF + off] = v;
    }
    red[t] = acc;
    __syncthreads();
    #pragma unroll
    for (int s = 128; s > 0; s >>= 1) {
        if (t < s) red[t] += red[t + s];
        __syncthreads();
    }
    if (t == 0) g_partials[blockIdx.x] = red[0];
}

// ---------------- kernel B2: parallel histogram ----------------
__global__ void hist_kernel() {
    __shared__ int h[NE];
    const int t = threadIdx.x;       // 32 blocks x 256 threads
    #pragma unroll
    for (int r = 0; r < 4; r++) h[t + 256 * r] = 0;
    __syncthreads();
    const int base = blockIdx.x * 1024;
    #pragma unroll
    for (int r = 0; r < 4; r++) {
        int id = g_idx[base + t + 256 * r];
        atomicAdd(&h[id], 1);
    }
    __syncthreads();
    #pragma unroll
    for (int r = 0; r < 4; r++) {
        int v = h[t + 256 * r];
        if (v) atomicAdd(&g_hist[t + 256 * r], v);
    }
}

// ---------------- kernel B3: loss + perplexity ----------------
__global__ void finalize_kernel(float* __restrict__ out) {
    __shared__ float red[1024];
    const int t = threadIdx.x;       // 1024 threads, 1 block
    red[t] = g_partials[t];
    __syncthreads();
    #pragma unroll
    for (int s = 512; s > 0; s >>= 1) {
        if (t < s) red[t] += red[t + s];
        __syncthreads();
    }
    float loss = red[0] * (1.0f + BETA) / 8388608.0f;
    __syncthreads();
    float p = (float)g_hist[t] / (float)NPIX;
    red[t] = p * logf(p + EPS_P);
    __syncthreads();
    #pragma unroll
    for (int s = 512; s > 0; s >>= 1) {
        if (t < s) red[t] += red[t + s];
        __syncthreads();
    }
    if (t == 0) {
        out[0] = loss;
        out[PERP_OFF] = expf(-red[0]);
    }
}

// ---------------- launch ----------------
extern "C" void kernel_launch(void* const* d_in, const int* in_sizes, int n_in,
                              void* d_out, int out_size) {
    const float* z   = (const float*)d_in[0];
    const float* emb = (const float*)d_in[1];
    float* out = (float*)d_out;

    split_kernel<<<NE, 256>>>(emb);
    dummy1_kernel<<<1, 32>>>();      // ncu alignment: argmin stays launch #4
    dummy2_kernel<<<1, 32>>>();

    cudaFuncSetAttribute(argmin_mma_kernel,
                         cudaFuncAttributeMaxDynamicSharedMemorySize, SMB_TOTAL);
    argmin_mma_kernel<<<NPIX / 256, 1024, SMB_TOTAL>>>(z);

    rescore_kernel<<<NPIX / 32, 256>>>(z, emb);
    gather_kernel<<<NPIX / 32, 256>>>(z, emb, out);
    hist_kernel<<<32, 256>>>();
    finalize_kernel<<<1, 1024>>>(out);
}

// round 14
// speedup vs baseline: 1.3905x; 1.0499x over previous
#include <cuda_runtime.h>
#include <cuda_fp16.h>
#include <math.h>
#include <stdint.h>

// ---------------- problem constants ----------------
#define NPIX     32768
#define NE       1024
#define KDIM     256
#define BETA     0.25f
#define EPS_P    1e-10f
#define DELTA    0.5f

// output layout (concatenated, float32)
#define ZQ_OFF    1ull
#define PERP_OFF  8388609ull
#define IDX_OFF   8388610ull
#define ZQ1_OFF   8421378ull

// ---------------- device scratch ----------------
__device__ int    g_idx[NPIX];
__device__ float  g_hn_g[NE];
__device__ int    g_hist[NE];
__device__ float  g_partials[1024];
__device__ int    g_cnt[NPIX];
__device__ int    g_cand[NPIX * 8];
// emb fp16, chunk-major packed: [64 chunks][128 codes][32 halfs], k perm16'd within 16-blocks
__device__ __half g_eh[64 * 128 * 32];

// ---------------- argmin smem byte offsets ----------------
#define SMB_AS    0            // 256 x 264 halfs = 135168
#define SMB_BS    135168       // 3 x (128 x 40 halfs) = 30720
#define SMB_STG   165888       // 32 x 264 floats = 33792
#define SMB_HN    199680       // 1024 floats
#define SMB_REDV  203776       // 256 x 4 floats = 4096
#define SMB_VS    207872       // 256 floats
#define SMB_TOTAL 208896
#define B_STAGE_H 5120

static __device__ __forceinline__ uint32_t smem_u32(const void* p) {
    uint32_t a;
    asm("{ .reg .u64 t; cvta.to.shared.u64 t, %1; cvt.u32.u64 %0, t; }" : "=r"(a) : "l"(p));
    return a;
}
static __device__ __forceinline__ void cp16(uint32_t smem, const void* g) {
    asm volatile("cp.async.cg.shared.global [%0], [%1], 16;" :: "r"(smem), "l"(g) : "memory");
}
#define CP_COMMIT() asm volatile("cp.async.commit_group;" ::: "memory")
#define CP_WAIT1()  asm volatile("cp.async.wait_group 1;" ::: "memory")
#define CP_WAIT0()  asm volatile("cp.async.wait_group 0;" ::: "memory")

// f16-accumulator MMA: D,C are 2x b32 (f16x2)
static __device__ __forceinline__ void mma16h(uint32_t* c, const uint32_t* a, uint32_t b0, uint32_t b1) {
    asm volatile(
        "mma.sync.aligned.m16n8k16.row.col.f16.f16.f16.f16 "
        "{%0,%1}, {%2,%3,%4,%5}, {%6,%7}, {%0,%1};"
        : "+r"(c[0]), "+r"(c[1])
        : "r"(a[0]), "r"(a[1]), "r"(a[2]), "r"(a[3]), "r"(b0), "r"(b1));
}

// permutation within 16-blocks so fragment k-quads {2qc,2qc+1,2qc+8,2qc+9} are contiguous
static __device__ __forceinline__ int perm16(int j) {
    return ((j >> 1) & 3) * 4 + ((j >> 3) & 1) * 2 + (j & 1);
}

// ---------------- dummy kernels (keep argmin as launch #4 for ncu) ----------------
__global__ void dummy1_kernel() {}
__global__ void dummy2_kernel() {}

// ---------------- kernel 0: emb -> fp16 chunk-major + half norms + zero ----------------
__global__ void split_kernel(const float* __restrict__ emb) {
    __shared__ float red[256];
    const int c = blockIdx.x;        // code 0..1023
    const int t = threadIdx.x;       // k 0..255
    float f = emb[c * KDIM + t];
    int chunk = (c >> 7) * 8 + (t >> 5);
    int within = (t & 16) + perm16(t & 15);
    g_eh[chunk * 4096 + (c & 127) * 32 + within] = __float2half_rn(f);
    red[t] = f * f;
    int gid = c * 256 + t;
    if (gid < NPIX) g_cnt[gid] = 0;
    __syncthreads();
    #pragma unroll
    for (int s = 128; s > 0; s >>= 1) {
        if (t < s) red[t] += red[t + s];
        __syncthreads();
    }
    if (t == 0) { g_hn_g[c] = 0.5f * red[0]; g_hist[c] = 0; }
}

// ---------------- kernel A: fp16 mma (f16 acc) approximate argmax, 1024 threads ----------------
// 32 warps = 8 M-groups x 4 N-groups; warp tile 32(M) x 32(N). MT=256 pixels/CTA.
// f16 accumulators (16 regs) + 4 pixel-row slots with depth-2 runner lists -> ~58 regs.
__global__ void __launch_bounds__(1024, 1)
argmin_mma_kernel(const float* __restrict__ z) {
    extern __shared__ char smc[];
    __half* As  = (__half*)(smc + SMB_AS);     // [256][264]
    __half* Bsb = (__half*)(smc + SMB_BS);     // 3 x [128][40]
    float* stg  = (float*)(smc + SMB_STG);     // [32][264]
    float* hn   = (float*)(smc + SMB_HN);
    float* redv = (float*)(smc + SMB_REDV);    // [256][4]
    float* Vs   = (float*)(smc + SMB_VS);
    const uint32_t sb = smem_u32(smc);

    const int tid = threadIdx.x;
    const int wid = tid >> 5;
    const int l   = tid & 31;
    const int qr  = l >> 2;
    const int qc  = l & 3;
    const int mb  = (wid >> 2) * 32;
    const int nb  = (wid & 3) * 32;
    const int m0  = blockIdx.x * 256;

    // B chunk loader: 8KB packed global -> padded smem stage (512 cp16 by lower half)
    auto load_chunk = [&](int it, int stage) {
        if (tid < 512) {
            const char* src = (const char*)g_eh + (size_t)it * 8192;
            uint32_t dst = sb + SMB_BS + stage * 10240;
            int code = tid >> 2, j = tid & 3;
            cp16(dst + code * 80 + j * 16, src + code * 64 + j * 16);
        }
        CP_COMMIT();
    };

    load_chunk(0, 0);
    load_chunk(1, 1);

    // ---- prologue: z (256 px x 256 k) -> fp16 As, k perm16'd ----
    {
        const float* zb = z + (size_t)(m0 >> 10) * (KDIM * 1024) + (m0 & 1023);
        const int m = tid & 255, hh = tid >> 8;   // hh 0..3
        for (int g = 0; g < 8; g++) {
            __syncthreads();
            #pragma unroll
            for (int r = 0; r < 2; r++) {
                int q = tid + 1024 * r;         // 0..2047 float4s
                int kk = q >> 6;                // 0..31
                int m4 = (q & 63) << 2;         // 0..252
                float4 v = *(const float4*)(zb + (size_t)(g * 32 + kk) * 1024 + m4);
                *(float4*)(stg + kk * 264 + m4) = v;
            }
            __syncthreads();
            #pragma unroll
            for (int pp = 0; pp < 4; pp++) {
                int p = hh * 4 + pp;            // 0..15 half2 pairs
                float f0 = stg[(2 * p) * 264 + m];
                float f1 = stg[(2 * p + 1) * 264 + m];
                int dest = ((p >> 3) & 1) * 16 + (p & 3) * 4 + ((p >> 2) & 1) * 2;
                __half2 h = __floats2half2_rn(f0, f1);
                *(__half2*)(As + m * 264 + g * 32 + dest) = h;
            }
        }
        hn[tid] = g_hn_g[tid];
    }
    __syncthreads();

    // 4 pixel-row slots (mf x reg-half), each with best + depth-2 runner list
    float best[4]; int bidx[4];
    float cv[4][2]; int ci[4][2];
    #pragma unroll
    for (int s = 0; s < 4; s++) {
        best[s] = -INFINITY; bidx[s] = 0;
        cv[s][0] = -INFINITY; cv[s][1] = -INFINITY;
        ci[s][0] = 0; ci[s][1] = 0;
    }

    for (int ct = 0; ct < 8; ct++) {
        uint32_t acc[2][4][2];
        #pragma unroll
        for (int mf = 0; mf < 2; mf++)
            #pragma unroll
            for (int nf = 0; nf < 4; nf++) { acc[mf][nf][0] = 0u; acc[mf][nf][1] = 0u; }

        for (int kc = 0; kc < 8; kc++) {
            const int it = ct * 8 + kc;
            const int stage = it % 3;
            if (it == 63) { CP_WAIT0(); } else { CP_WAIT1(); }
            __syncthreads();
            if (it + 2 < 64) load_chunk(it + 2, (it + 2) % 3);

            const __half* B = Bsb + stage * B_STAGE_H;

            #pragma unroll
            for (int ks = 0; ks < 2; ks++) {
                uint32_t af[2][4];
                #pragma unroll
                for (int mf = 0; mf < 2; mf++) {
                    int r0 = mb + qr + mf * 16;
                    uint2 A1 = *(const uint2*)(As + r0 * 264 + kc * 32 + ks * 16 + qc * 4);
                    uint2 A2 = *(const uint2*)(As + (r0 + 8) * 264 + kc * 32 + ks * 16 + qc * 4);
                    af[mf][0] = A1.x; af[mf][2] = A1.y;
                    af[mf][1] = A2.x; af[mf][3] = A2.y;
                }
                #pragma unroll
                for (int nf = 0; nf < 4; nf++) {
                    int n = nb + nf * 8 + qr;
                    uint2 B2 = *(const uint2*)(B + n * 40 + ks * 16 + qc * 4);
                    mma16h(acc[0][nf], af[0], B2.x, B2.y);
                    mma16h(acc[1][nf], af[1], B2.x, B2.y);
                }
            }
        }

        // epilogue: unpack f16 scores, subtract half-norm, fold into argmax + candidates
        #pragma unroll
        for (int mf = 0; mf < 2; mf++)
            #pragma unroll
            for (int nf = 0; nf < 4; nf++)
                #pragma unroll
                for (int rg = 0; rg < 2; rg++) {
                    float2 sc = __half22float2(*(__half2*)&acc[mf][nf][rg]);
                    int slot = mf * 2 + rg;
                    #pragma unroll
                    for (int hl = 0; hl < 2; hl++) {
                        int col = nb + nf * 8 + 2 * qc + hl;
                        int code = ct * 128 + col;
                        float s = (hl ? sc.y : sc.x) - hn[code];
                        if (s > best[slot]) {
                            float ov = best[slot]; int oi = bidx[slot];
                            if (cv[slot][0] <= cv[slot][1]) {
                                if (ov > cv[slot][0]) { cv[slot][0] = ov; ci[slot][0] = oi; }
                            } else {
                                if (ov > cv[slot][1]) { cv[slot][1] = ov; ci[slot][1] = oi; }
                            }
                            best[slot] = s; bidx[slot] = code;
                        } else if (s > best[slot] - DELTA) {
                            if (cv[slot][0] <= cv[slot][1]) {
                                if (s > cv[slot][0]) { cv[slot][0] = s; ci[slot][0] = code; }
                            } else {
                                if (s > cv[slot][1]) { cv[slot][1] = s; ci[slot][1] = code; }
                            }
                        }
                    }
                }
    }

    // per-pixel approx max: qc-lane reduce, then the 4 N-warps via smem
    #pragma unroll
    for (int s = 0; s < 4; s++) {
        float v = best[s];
        #pragma unroll
        for (int m = 1; m <= 2; m <<= 1) {
            float ov = __shfl_xor_sync(0xffffffffu, v, m);
            if (ov > v) v = ov;
        }
        if (qc == 0) {
            int row = mb + qr + (s >> 1) * 16 + (s & 1) * 8;
            redv[row * 4 + (wid & 3)] = v;
        }
    }
    __syncthreads();
    if (tid < 256) {
        Vs[tid] = fmaxf(fmaxf(redv[tid * 4], redv[tid * 4 + 1]),
                        fmaxf(redv[tid * 4 + 2], redv[tid * 4 + 3]));
    }
    __syncthreads();

    // emit candidates within DELTA of pixel approx max
    #pragma unroll
    for (int s = 0; s < 4; s++) {
        int row = mb + qr + (s >> 1) * 16 + (s & 1) * 8;
        float V = Vs[row];
        int p = m0 + row;
        if (best[s] > V - DELTA) {
            int pos = atomicAdd(&g_cnt[p], 1);
            if (pos < 8) g_cand[p * 8 + pos] = bidx[s];
        }
        if (cv[s][0] > V - DELTA) {
            int pos = atomicAdd(&g_cnt[p], 1);
            if (pos < 8) g_cand[p * 8 + pos] = ci[s][0];
        }
        if (cv[s][1] > V - DELTA) {
            int pos = atomicAdd(&g_cnt[p], 1);
            if (pos < 8) g_cand[p * 8 + pos] = ci[s][1];
        }
    }
}

// ---------------- kernel A2: exact fp32 rescoring (smem-staged z, coalesced) ----------------
__global__ void __launch_bounds__(256)
rescore_kernel(const float* __restrict__ z, const float* __restrict__ emb) {
    __shared__ float zs[32][257];
    const int t = threadIdx.x;
    const int w = t >> 5;
    const int l = t & 31;
    const int n0 = blockIdx.x * 32;
    const int b = n0 >> 10;
    const float* zb = z + (size_t)b * (KDIM * 1024) + (n0 & 1023);
    #pragma unroll
    for (int r = 0; r < 8; r++) {
        int q = t + 256 * r;            // 0..2047
        int kk = q >> 3;                // 0..255
        int h4 = (q & 7) << 2;          // 0..28
        float4 v = *(const float4*)(zb + (size_t)kk * 1024 + h4);
        zs[h4 + 0][kk] = v.x; zs[h4 + 1][kk] = v.y;
        zs[h4 + 2][kk] = v.z; zs[h4 + 3][kk] = v.w;
    }
    __syncthreads();
    #pragma unroll
    for (int px = 0; px < 4; px++) {
        int pix = w * 4 + px;
        int p = n0 + pix;
        int cnt = g_cnt[p];
        if (cnt > 8) cnt = 8;
        float bestv = -INFINITY;
        int besti = 0;
        for (int c = 0; c < cnt; c++) {
            int idx = g_cand[p * 8 + c];
            const float* e = emb + (size_t)idx * KDIM;
            float acc = 0.0f;
            #pragma unroll
            for (int j = 0; j < 8; j++)
                acc = fmaf(zs[pix][j * 32 + l], e[j * 32 + l], acc);
            #pragma unroll
            for (int m = 16; m >= 1; m >>= 1)
                acc += __shfl_xor_sync(0xffffffffu, acc, m);
            float s = acc - g_hn_g[idx];
            if (s > bestv || (s == bestv && idx < besti)) { bestv = s; besti = idx; }
        }
        if (l == 0) g_idx[p] = besti;
    }
}

// ---------------- kernel B1: gather z_q/z_q1 + squared-error partials + idx out ----------------
__global__ void __launch_bounds__(256)
gather_kernel(const float* __restrict__ z, const float* __restrict__ emb,
              float* __restrict__ out) {
    __shared__ float se[32][257];
    __shared__ int sidx[32];
    __shared__ float red[256];
    const int t = threadIdx.x;
    const int n0 = blockIdx.x * 32;
    if (t < 32) sidx[t] = g_idx[n0 + t];
    __syncthreads();
    if (t < 32) out[IDX_OFF + n0 + t] = (float)sidx[t];
    #pragma unroll
    for (int r = 0; r < 8; r++) {
        int q = t + 256 * r;
        int row = q >> 6;
        int c4 = (q & 63) << 2;
        float4 v = *(const float4*)(emb + (size_t)sidx[row] * KDIM + c4);
        se[row][c4 + 0] = v.x; se[row][c4 + 1] = v.y;
        se[row][c4 + 2] = v.z; se[row][c4 + 3] = v.w;
    }
    __syncthreads();
    const int hw = t & 31;
    const int cg = t >> 5;
    const int b = n0 >> 10;
    const int hwg = (n0 & 1023) + hw;
    const size_t zbase = (size_t)b * (KDIM * 1024) + hwg;
    float acc = 0.0f;
    #pragma unroll
    for (int ci2 = 0; ci2 < 32; ci2++) {
        int c = cg * 32 + ci2;
        float v = se[hw][c];
        size_t off = zbase + (size_t)c * 1024;
        float zv = z[off];
        float d = v - zv;
        acc += d * d;
        out[ZQ_OFF + off] = v;
        out[ZQ1_OFF + off] = v;
    }
    red[t] = acc;
    __syncthreads();
    #pragma unroll
    for (int s = 128; s > 0; s >>= 1) {
        if (t < s) red[t] += red[t + s];
        __syncthreads();
    }
    if (t == 0) g_partials[blockIdx.x] = red[0];
}

// ---------------- kernel B2: parallel histogram ----------------
__global__ void hist_kernel() {
    __shared__ int h[NE];
    const int t = threadIdx.x;       // 32 blocks x 256 threads
    #pragma unroll
    for (int r = 0; r < 4; r++) h[t + 256 * r] = 0;
    __syncthreads();
    const int base = blockIdx.x * 1024;
    #pragma unroll
    for (int r = 0; r < 4; r++) {
        int id = g_idx[base + t + 256 * r];
        atomicAdd(&h[id], 1);
    }
    __syncthreads();
    #pragma unroll
    for (int r = 0; r < 4; r++) {
        int v = h[t + 256 * r];
        if (v) atomicAdd(&g_hist[t + 256 * r], v);
    }
}

// ---------------- kernel B3: loss + perplexity ----------------
__global__ void finalize_kernel(float* __restrict__ out) {
    __shared__ float red[1024];
    const int t = threadIdx.x;       // 1024 threads, 1 block
    red[t] = g_partials[t];
    __syncthreads();
    #pragma unroll
    for (int s = 512; s > 0; s >>= 1) {
        if (t < s) red[t] += red[t + s];
        __syncthreads();
    }
    float loss = red[0] * (1.0f + BETA) / 8388608.0f;
    __syncthreads();
    float p = (float)g_hist[t] / (float)NPIX;
    red[t] = p * logf(p + EPS_P);
    __syncthreads();
    #pragma unroll
    for (int s = 512; s > 0; s >>= 1) {
        if (t < s) red[t] += red[t + s];
        __syncthreads();
    }
    if (t == 0) {
        out[0] = loss;
        out[PERP_OFF] = expf(-red[0]);
    }
}

// ---------------- launch ----------------
extern "C" void kernel_launch(void* const* d_in, const int* in_sizes, int n_in,
                              void* d_out, int out_size) {
    const float* z   = (const float*)d_in[0];
    const float* emb = (const float*)d_in[1];
    float* out = (float*)d_out;

    split_kernel<<<NE, 256>>>(emb);
    dummy1_kernel<<<1, 32>>>();      // ncu alignment: argmin stays launch #4
    dummy2_kernel<<<1, 32>>>();

    cudaFuncSetAttribute(argmin_mma_kernel,
                         cudaFuncAttributeMaxDynamicSharedMemorySize, SMB_TOTAL);
    argmin_mma_kernel<<<NPIX / 256, 1024, SMB_TOTAL>>>(z);

    rescore_kernel<<<NPIX / 32, 256>>>(z, emb);
    gather_kernel<<<NPIX / 32, 256>>>(z, emb, out);
    hist_kernel<<<32, 256>>>();
    finalize_kernel<<<1, 1024>>>(out);
}

// round 16
// speedup vs baseline: 1.7206x; 1.2374x over previous
#include <cuda_runtime.h>
#include <cuda_fp16.h>
#include <math.h>
#include <stdint.h>

// ---------------- problem constants ----------------
#define NPIX     32768
#define NE       1024
#define KDIM     256
#define BETA     0.25f
#define EPS_P    1e-10f
#define DELTA    0.5f

// output layout (concatenated, float32)
#define ZQ_OFF    1ull
#define PERP_OFF  8388609ull
#define IDX_OFF   8388610ull
#define ZQ1_OFF   8421378ull

// ---------------- device scratch ----------------
__device__ int    g_idx[NPIX];
__device__ float  g_hn_g[NE];
__device__ int    g_hist[NE];
__device__ float  g_partials[1024];
__device__ int    g_cnt[NPIX];
__device__ int    g_cand[NPIX * 8];
// emb fp16, chunk-major packed: [64 chunks][128 codes][32 halfs], k perm16'd within 16-blocks
__device__ __half g_eh[64 * 128 * 32];

// ---------------- argmin smem byte offsets ----------------
#define SMB_AS    0            // 256 x 264 halfs = 135168
#define SMB_BS    135168       // 6 stages x (128 x 40 halfs = 10240 B) = 61440
#define SMB_STG   (SMB_BS + 20480)   // stg aliases stages 2..5 (33792 B <= 40960)
#define SMB_HN    196608       // 1024 floats
#define SMB_REDV  200704       // 256 x 4 floats = 4096
#define SMB_VS    204800       // 256 floats
#define SMB_TOTAL 205824

static __device__ __forceinline__ uint32_t smem_u32(const void* p) {
    uint32_t a;
    asm("{ .reg .u64 t; cvta.to.shared.u64 t, %1; cvt.u32.u64 %0, t; }" : "=r"(a) : "l"(p));
    return a;
}
static __device__ __forceinline__ void cp16(uint32_t smem, const void* g) {
    asm volatile("cp.async.cg.shared.global [%0], [%1], 16;" :: "r"(smem), "l"(g) : "memory");
}
#define CP_COMMIT() asm volatile("cp.async.commit_group;" ::: "memory")
#define CP_WAIT2()  asm volatile("cp.async.wait_group 2;" ::: "memory")
#define CP_WAIT0()  asm volatile("cp.async.wait_group 0;" ::: "memory")

// f16-accumulator MMA: D,C are 2x b32 (f16x2)
static __device__ __forceinline__ void mma16h(uint32_t* c, const uint32_t* a, uint32_t b0, uint32_t b1) {
    asm volatile(
        "mma.sync.aligned.m16n8k16.row.col.f16.f16.f16.f16 "
        "{%0,%1}, {%2,%3,%4,%5}, {%6,%7}, {%0,%1};"
        : "+r"(c[0]), "+r"(c[1])
        : "r"(a[0]), "r"(a[1]), "r"(a[2]), "r"(a[3]), "r"(b0), "r"(b1));
}

static __device__ __forceinline__ void ldsm4(uint32_t* r, uint32_t addr) {
    asm volatile("ldmatrix.sync.aligned.m8n8.x4.shared.b16 {%0,%1,%2,%3}, [%4];"
                 : "=r"(r[0]), "=r"(r[1]), "=r"(r[2]), "=r"(r[3]) : "r"(addr));
}

// permutation within 16-blocks (same relabeling applied to A and B -> mma-consistent)
static __device__ __forceinline__ int perm16(int j) {
    return ((j >> 1) & 3) * 4 + ((j >> 3) & 1) * 2 + (j & 1);
}

// ---------------- dummy kernels (keep argmin as launch #4 for ncu) ----------------
__global__ void dummy1_kernel() {}
__global__ void dummy2_kernel() {}

// ---------------- kernel 0: emb -> fp16 chunk-major + half norms + zero ----------------
__global__ void split_kernel(const float* __restrict__ emb) {
    __shared__ float red[256];
    const int c = blockIdx.x;        // code 0..1023
    const int t = threadIdx.x;       // k 0..255
    float f = emb[c * KDIM + t];
    int chunk = (c >> 7) * 8 + (t >> 5);
    int within = (t & 16) + perm16(t & 15);
    g_eh[chunk * 4096 + (c & 127) * 32 + within] = __float2half_rn(f);
    red[t] = f * f;
    int gid = c * 256 + t;
    if (gid < NPIX) g_cnt[gid] = 0;
    __syncthreads();
    #pragma unroll
    for (int s = 128; s > 0; s >>= 1) {
        if (t < s) red[t] += red[t + s];
        __syncthreads();
    }
    if (t == 0) { g_hn_g[c] = 0.5f * red[0]; g_hist[c] = 0; }
}

// ---------------- kernel A: fp16 mma (f16 acc) approximate argmax, 1024 threads ----------------
// 32 warps = 8 M-groups x 4 N-groups; warp tile 32(M) x 32(N). MT=256 pixels/CTA.
// ldmatrix fragment loads + paired-chunk 6-stage cp.async pipeline (32 syncs).
__global__ void __launch_bounds__(1024, 1)
argmin_mma_kernel(const float* __restrict__ z) {
    extern __shared__ char smc[];
    __half* As  = (__half*)(smc + SMB_AS);     // [256][264]
    float* stg  = (float*)(smc + SMB_STG);     // [32][264] (aliases stages 2..5)
    float* hn   = (float*)(smc + SMB_HN);
    float* redv = (float*)(smc + SMB_REDV);    // [256][4]
    float* Vs   = (float*)(smc + SMB_VS);
    const uint32_t sb = smem_u32(smc);

    const int tid = threadIdx.x;
    const int wid = tid >> 5;
    const int l   = tid & 31;
    const int qr  = l >> 2;
    const int qc  = l & 3;
    const int mb  = (wid >> 2) * 32;
    const int nb  = (wid & 3) * 32;
    const int m0  = blockIdx.x * 256;

    // ldmatrix lane base addresses (bytes)
    const uint32_t aBase = sb + SMB_AS + (uint32_t)(mb + (l & 15)) * 528 + ((l >> 4) & 1) * 16;
    const uint32_t bBase = sb + SMB_BS + (uint32_t)(nb + (l & 7) + ((l >> 4) & 1) * 8) * 80
                           + ((l >> 3) & 1) * 16;

    // B chunk loader: 8KB packed global -> padded smem stage (512 cp16 by lower half)
    auto load_chunk = [&](int it) {
        if (tid < 512) {
            const char* src = (const char*)g_eh + (size_t)it * 8192;
            uint32_t dst = sb + SMB_BS + (it % 6) * 10240;
            int code = tid >> 2, j = tid & 3;
            cp16(dst + code * 80 + j * 16, src + code * 64 + j * 16);
        }
        CP_COMMIT();
    };

    // prefetch chunks 0,1 (stages 0,1 — NOT aliased by stg)
    load_chunk(0);
    load_chunk(1);

    // ---- prologue: z (256 px x 256 k) -> fp16 As, k perm16'd ----
    {
        const float* zb = z + (size_t)(m0 >> 10) * (KDIM * 1024) + (m0 & 1023);
        const int m = tid & 255, hh = tid >> 8;   // hh 0..3
        for (int g = 0; g < 8; g++) {
            __syncthreads();
            #pragma unroll
            for (int r = 0; r < 2; r++) {
                int q = tid + 1024 * r;         // 0..2047 float4s
                int kk = q >> 6;                // 0..31
                int m4 = (q & 63) << 2;         // 0..252
                float4 v = *(const float4*)(zb + (size_t)(g * 32 + kk) * 1024 + m4);
                *(float4*)(stg + kk * 264 + m4) = v;
            }
            __syncthreads();
            #pragma unroll
            for (int pp = 0; pp < 4; pp++) {
                int p = hh * 4 + pp;            // 0..15 half2 pairs
                float f0 = stg[(2 * p) * 264 + m];
                float f1 = stg[(2 * p + 1) * 264 + m];
                int dest = ((p >> 3) & 1) * 16 + (p & 3) * 4 + ((p >> 2) & 1) * 2;
                __half2 h = __floats2half2_rn(f0, f1);
                *(__half2*)(As + m * 264 + g * 32 + dest) = h;
            }
        }
        hn[tid] = g_hn_g[tid];
    }
    __syncthreads();      // prologue fully done (stg reads complete) before stages 2,3 get written

    load_chunk(2);
    load_chunk(3);

    // 4 pixel-row slots (mf x reg-half), each with best + depth-2 runner list
    float best[4]; int bidx[4];
    float cv[4][2]; int ci[4][2];
    #pragma unroll
    for (int s = 0; s < 4; s++) {
        best[s] = -INFINITY; bidx[s] = 0;
        cv[s][0] = -INFINITY; cv[s][1] = -INFINITY;
        ci[s][0] = 0; ci[s][1] = 0;
    }

    for (int ct = 0; ct < 8; ct++) {
        uint32_t acc[2][4][2];
        #pragma unroll
        for (int mf = 0; mf < 2; mf++)
            #pragma unroll
            for (int nf = 0; nf < 4; nf++) { acc[mf][nf][0] = 0u; acc[mf][nf][1] = 0u; }

        for (int kp = 0; kp < 4; kp++) {           // pairs of chunks
            const int p  = ct * 4 + kp;            // global pair 0..31
            const int c0 = 2 * p;                  // global chunks
            if (p == 31) { CP_WAIT0(); } else { CP_WAIT2(); }
            __syncthreads();
            if (c0 + 4 < 64) load_chunk(c0 + 4);
            if (c0 + 5 < 64) load_chunk(c0 + 5);

            // compute the two chunks of this pair
            #pragma unroll
            for (int half = 0; half < 2; half++) {
                const int kc = 2 * kp + half;           // within-ct chunk 0..7
                const uint32_t bStage = bBase + ((uint32_t)((c0 + half) % 6)) * 10240;
                const uint32_t aCol = (uint32_t)kc * 64;
                #pragma unroll
                for (int ks = 0; ks < 2; ks++) {
                    uint32_t a0[4], a1[4], bfr[8];
                    ldsm4(a0, aBase + aCol + ks * 32);
                    ldsm4(a1, aBase + 8448 + aCol + ks * 32);
                    ldsm4(bfr,     bStage + ks * 32);
                    ldsm4(bfr + 4, bStage + 1280 + ks * 32);
                    mma16h(acc[0][0], a0, bfr[0], bfr[1]);
                    mma16h(acc[0][1], a0, bfr[2], bfr[3]);
                    mma16h(acc[0][2], a0, bfr[4], bfr[5]);
                    mma16h(acc[0][3], a0, bfr[6], bfr[7]);
                    mma16h(acc[1][0], a1, bfr[0], bfr[1]);
                    mma16h(acc[1][1], a1, bfr[2], bfr[3]);
                    mma16h(acc[1][2], a1, bfr[4], bfr[5]);
                    mma16h(acc[1][3], a1, bfr[6], bfr[7]);
                }
            }
        }

        // epilogue: unpack f16 scores, subtract half-norm, fold into argmax + candidates
        #pragma unroll
        for (int mf = 0; mf < 2; mf++)
            #pragma unroll
            for (int nf = 0; nf < 4; nf++)
                #pragma unroll
                for (int rg = 0; rg < 2; rg++) {
                    float2 sc = __half22float2(*(__half2*)&acc[mf][nf][rg]);
                    int slot = mf * 2 + rg;
                    #pragma unroll
                    for (int hl = 0; hl < 2; hl++) {
                        int col = nb + nf * 8 + 2 * qc + hl;
                        int code = ct * 128 + col;
                        float s = (hl ? sc.y : sc.x) - hn[code];
                        if (s > best[slot]) {
                            float ov = best[slot]; int oi = bidx[slot];
                            if (cv[slot][0] <= cv[slot][1]) {
                                if (ov > cv[slot][0]) { cv[slot][0] = ov; ci[slot][0] = oi; }
                            } else {
                                if (ov > cv[slot][1]) { cv[slot][1] = ov; ci[slot][1] = oi; }
                            }
                            best[slot] = s; bidx[slot] = code;
                        } else if (s > best[slot] - DELTA) {
                            if (cv[slot][0] <= cv[slot][1]) {
                                if (s > cv[slot][0]) { cv[slot][0] = s; ci[slot][0] = code; }
                            } else {
                                if (s > cv[slot][1]) { cv[slot][1] = s; ci[slot][1] = code; }
                            }
                        }
                    }
                }
    }

    // per-pixel approx max: qc-lane reduce, then the 4 N-warps via smem
    #pragma unroll
    for (int s = 0; s < 4; s++) {
        float v = best[s];
        #pragma unroll
        for (int m = 1; m <= 2; m <<= 1) {
            float ov = __shfl_xor_sync(0xffffffffu, v, m);
            if (ov > v) v = ov;
        }
        if (qc == 0) {
            int row = mb + qr + (s >> 1) * 16 + (s & 1) * 8;
            redv[row * 4 + (wid & 3)] = v;
        }
    }
    __syncthreads();
    if (tid < 256) {
        Vs[tid] = fmaxf(fmaxf(redv[tid * 4], redv[tid * 4 + 1]),
                        fmaxf(redv[tid * 4 + 2], redv[tid * 4 + 3]));
    }
    __syncthreads();

    // emit candidates within DELTA of pixel approx max
    #pragma unroll
    for (int s = 0; s < 4; s++) {
        int row = mb + qr + (s >> 1) * 16 + (s & 1) * 8;
        float V = Vs[row];
        int p = m0 + row;
        if (best[s] > V - DELTA) {
            int pos = atomicAdd(&g_cnt[p], 1);
            if (pos < 8) g_cand[p * 8 + pos] = bidx[s];
        }
        if (cv[s][0] > V - DELTA) {
            int pos = atomicAdd(&g_cnt[p], 1);
            if (pos < 8) g_cand[p * 8 + pos] = ci[s][0];
        }
        if (cv[s][1] > V - DELTA) {
            int pos = atomicAdd(&g_cnt[p], 1);
            if (pos < 8) g_cand[p * 8 + pos] = ci[s][1];
        }
    }
}

// ---------------- kernel A2: exact fp32 rescoring (smem-staged z, coalesced) ----------------
__global__ void __launch_bounds__(256)
rescore_kernel(const float* __restrict__ z, const float* __restrict__ emb) {
    __shared__ float zs[32][257];
    const int t = threadIdx.x;
    const int w = t >> 5;
    const int l = t & 31;
    const int n0 = blockIdx.x * 32;
    const int b = n0 >> 10;
    const float* zb = z + (size_t)b * (KDIM * 1024) + (n0 & 1023);
    #pragma unroll
    for (int r = 0; r < 8; r++) {
        int q = t + 256 * r;            // 0..2047
        int kk = q >> 3;                // 0..255
        int h4 = (q & 7) << 2;          // 0..28
        float4 v = *(const float4*)(zb + (size_t)kk * 1024 + h4);
        zs[h4 + 0][kk] = v.x; zs[h4 + 1][kk] = v.y;
        zs[h4 + 2][kk] = v.z; zs[h4 + 3][kk] = v.w;
    }
    __syncthreads();
    #pragma unroll
    for (int px = 0; px < 4; px++) {
        int pix = w * 4 + px;
        int p = n0 + pix;
        int cnt = g_cnt[p];
        if (cnt > 8) cnt = 8;
        float bestv = -INFINITY;
        int besti = 0;
        for (int c = 0; c < cnt; c++) {
            int idx = g_cand[p * 8 + c];
            const float* e = emb + (size_t)idx * KDIM;
            float acc = 0.0f;
            #pragma unroll
            for (int j = 0; j < 8; j++)
                acc = fmaf(zs[pix][j * 32 + l], e[j * 32 + l], acc);
            #pragma unroll
            for (int m = 16; m >= 1; m >>= 1)
                acc += __shfl_xor_sync(0xffffffffu, acc, m);
            float s = acc - g_hn_g[idx];
            if (s > bestv || (s == bestv && idx < besti)) { bestv = s; besti = idx; }
        }
        if (l == 0) g_idx[p] = besti;
    }
}

// ---------------- kernel B1: gather z_q/z_q1 + squared-error partials + idx out ----------------
__global__ void __launch_bounds__(256)
gather_kernel(const float* __restrict__ z, const float* __restrict__ emb,
              float* __restrict__ out) {
    __shared__ float se[32][257];
    __shared__ int sidx[32];
    __shared__ float red[256];
    const int t = threadIdx.x;
    const int n0 = blockIdx.x * 32;
    if (t < 32) sidx[t] = g_idx[n0 + t];
    __syncthreads();
    if (t < 32) out[IDX_OFF + n0 + t] = (float)sidx[t];
    #pragma unroll
    for (int r = 0; r < 8; r++) {
        int q = t + 256 * r;
        int row = q >> 6;
        int c4 = (q & 63) << 2;
        float4 v = *(const float4*)(emb + (size_t)sidx[row] * KDIM + c4);
        se[row][c4 + 0] = v.x; se[row][c4 + 1] = v.y;
        se[row][c4 + 2] = v.z; se[row][c4 + 3] = v.w;
    }
    __syncthreads();
    const int hw = t & 31;
    const int cg = t >> 5;
    const int b = n0 >> 10;
    const int hwg = (n0 & 1023) + hw;
    const size_t zbase = (size_t)b * (KDIM * 1024) + hwg;
    float acc = 0.0f;
    #pragma unroll
    for (int ci2 = 0; ci2 < 32; ci2++) {
        int c = cg * 32 + ci2;
        float v = se[hw][c];
        size_t off = zbase + (size_t)c * 1024;
        float zv = z[off];
        float d = v - zv;
        acc += d * d;
        out[ZQ_OFF + off] = v;
        out[ZQ1_OFF + off] = v;
    }
    red[t] = acc;
    __syncthreads();
    #pragma unroll
    for (int s = 128; s > 0; s >>= 1) {
        if (t < s) red[t] += red[t + s];
        __syncthreads();
    }
    if (t == 0) g_partials[blockIdx.x] = red[0];
}

// ---------------- kernel B2: parallel histogram ----------------
__global__ void hist_kernel() {
    __shared__ int h[NE];
    const int t = threadIdx.x;       // 32 blocks x 256 threads
    #pragma unroll
    for (int r = 0; r < 4; r++) h[t + 256 * r] = 0;
    __syncthreads();
    const int base = blockIdx.x * 1024;
    #pragma unroll
    for (int r = 0; r < 4; r++) {
        int id = g_idx[base + t + 256 * r];
        atomicAdd(&h[id], 1);
    }
    __syncthreads();
    #pragma unroll
    for (int r = 0; r < 4; r++) {
        int v = h[t + 256 * r];
        if (v) atomicAdd(&g_hist[t + 256 * r], v);
    }
}

// ---------------- kernel B3: loss + perplexity ----------------
__global__ void finalize_kernel(float* __restrict__ out) {
    __shared__ float red[1024];
    const int t = threadIdx.x;       // 1024 threads, 1 block
    red[t] = g_partials[t];
    __syncthreads();
    #pragma unroll
    for (int s = 512; s > 0; s >>= 1) {
        if (t < s) red[t] += red[t + s];
        __syncthreads();
    }
    float loss = red[0] * (1.0f + BETA) / 8388608.0f;
    __syncthreads();
    float p = (float)g_hist[t] / (float)NPIX;
    red[t] = p * logf(p + EPS_P);
    __syncthreads();
    #pragma unroll
    for (int s = 512; s > 0; s >>= 1) {
        if (t < s) red[t] += red[t + s];
        __syncthreads();
    }
    if (t == 0) {
        out[0] = loss;
        out[PERP_OFF] = expf(-red[0]);
    }
}

// ---------------- launch ----------------
extern "C" void kernel_launch(void* const* d_in, const int* in_sizes, int n_in,
                              void* d_out, int out_size) {
    const float* z   = (const float*)d_in[0];
    const float* emb = (const float*)d_in[1];
    float* out = (float*)d_out;

    split_kernel<<<NE, 256>>>(emb);
    dummy1_kernel<<<1, 32>>>();      // ncu alignment: argmin stays launch #4
    dummy2_kernel<<<1, 32>>>();

    cudaFuncSetAttribute(argmin_mma_kernel,
                         cudaFuncAttributeMaxDynamicSharedMemorySize, SMB_TOTAL);
    argmin_mma_kernel<<<NPIX / 256, 1024, SMB_TOTAL>>>(z);

    rescore_kernel<<<NPIX / 32, 256>>>(z, emb);
    gather_kernel<<<NPIX / 32, 256>>>(z, emb, out);
    hist_kernel<<<32, 256>>>();
    finalize_kernel<<<1, 1024>>>(out);
}